// round 3
// baseline (speedup 1.0000x reference)
#include <cuda_runtime.h>
#include <math.h>

#define Bb   8
#define Ss   1024
#define Dd   768
#define Hh   12
#define HDh  64
#define DFF  3072
#define LL   6

// ---------------- scratch ----------------
__device__ float gX [Bb*Ss*Dd];
__device__ float gQ [Bb*Ss*Dd];
__device__ float gK [Bb*Ss*Dd];
__device__ float gV [Bb*Ss*Dd];
__device__ float gS [100663296];         // B*H*S*S scores (402 MB)
__device__ float gHb[Bb*Ss*Dd];
__device__ float gY1[Bb*Ss*Dd];
__device__ float gF [Bb*Ss*DFF];

// ---------------- helpers ----------------
__device__ __forceinline__ unsigned f2tf32(float f) {
    unsigned u;
    asm("cvt.rna.tf32.f32 %0, %1;" : "=r"(u) : "f"(f));
    return u;
}

__device__ __forceinline__ void mma_tf32(float c[4], unsigned a0, unsigned a1, unsigned a2, unsigned a3,
                                         unsigned b0, unsigned b1) {
    asm volatile(
        "mma.sync.aligned.m16n8k8.row.col.f32.tf32.tf32.f32 "
        "{%0,%1,%2,%3}, {%4,%5,%6,%7}, {%8,%9}, {%0,%1,%2,%3};\n"
        : "+f"(c[0]), "+f"(c[1]), "+f"(c[2]), "+f"(c[3])
        : "r"(a0), "r"(a1), "r"(a2), "r"(a3), "r"(b0), "r"(b1));
}

union U8 { uint4 v[2]; unsigned u[8]; };

__device__ __forceinline__ float blockReduceSum(float v) {
    __shared__ float red[32];
    #pragma unroll
    for (int o = 16; o > 0; o >>= 1) v += __shfl_xor_sync(0xffffffffu, v, o);
    int lane = threadIdx.x & 31, w = threadIdx.x >> 5;
    if (lane == 0) red[w] = v;
    __syncthreads();
    v = (threadIdx.x < 8) ? red[threadIdx.x] : 0.f;
    if (w == 0) {
        #pragma unroll
        for (int o = 4; o > 0; o >>= 1) v += __shfl_xor_sync(0xffffffffu, v, o);
        if (lane == 0) red[0] = v;
    }
    __syncthreads();
    float r = red[0];
    __syncthreads();
    return r;
}

__device__ __forceinline__ float blockReduceMax(float v) {
    __shared__ float red[32];
    #pragma unroll
    for (int o = 16; o > 0; o >>= 1) v = fmaxf(v, __shfl_xor_sync(0xffffffffu, v, o));
    int lane = threadIdx.x & 31, w = threadIdx.x >> 5;
    if (lane == 0) red[w] = v;
    __syncthreads();
    v = (threadIdx.x < 8) ? red[threadIdx.x] : -3.4e38f;
    if (w == 0) {
        #pragma unroll
        for (int o = 4; o > 0; o >>= 1) v = fmaxf(v, __shfl_xor_sync(0xffffffffu, v, o));
        if (lane == 0) red[0] = v;
    }
    __syncthreads();
    float r = red[0];
    __syncthreads();
    return r;
}

// ---------------- embedding ----------------
__global__ void embed_kernel(const int* __restrict__ ids, const float* __restrict__ emb,
                             const float* __restrict__ pe, float* __restrict__ x) {
    int i  = blockIdx.x * blockDim.x + threadIdx.x;
    int d  = i % Dd;
    int bs = i / Dd;
    int s  = bs % Ss;
    x[i] = emb[(size_t)ids[bs] * Dd + d] + pe[(size_t)s * Dd + d];
}

// ============ TF32 NT GEMM: C = A[M,K] @ B[N,K]^T (*scale, +bias, relu) ============
// BM=128, BN=128, BK=32, 256 threads, warp tiles 64x32, double-buffered smem,
// k-permuted smem layout: slot = (k&3)*8 + (k>>2)  ->  LDS.128 fragment loads.
template<bool BIAS, bool RELU>
__global__ __launch_bounds__(256, 1) void gemm_tf32_nt(
    int M, int N, int K,
    const float* __restrict__ A, int lda, long az,
    const float* __restrict__ B, int ldb, long bz,
    float* __restrict__ C, int ldc, long cz,
    const float* __restrict__ bias, float scale)
{
    extern __shared__ unsigned sm[];
    unsigned* AsBase = sm;                 // [2][128*36]
    unsigned* BsBase = sm + 2 * 128 * 36;  // [2][128*36]

    const int z = blockIdx.z;
    const float* Ap = A + (size_t)az * z + (size_t)(blockIdx.y * 128) * lda;
    const float* Bp = B + (size_t)bz * z + (size_t)(blockIdx.x * 128) * ldb;
    const int tid = threadIdx.x;
    const int lane = tid & 31, warp = tid >> 5;
    const int wm = (warp >> 2) * 64, wn = (warp & 3) * 32;
    const int grp = lane >> 2, tig = lane & 3;
    const int lrow = tid >> 3;            // 0..31
    const int lc4  = (tid & 7) * 4;       // 0..28

    float4 ra[4], rb[4];
    float acc[4][4][4] = {};

    auto LDG = [&](int k0) {
        #pragma unroll
        for (int p = 0; p < 4; p++) {
            ra[p] = *(const float4*)(Ap + (size_t)(lrow + p * 32) * lda + k0 + lc4);
            rb[p] = *(const float4*)(Bp + (size_t)(lrow + p * 32) * ldb + k0 + lc4);
        }
    };
    auto STS = [&](int buf) {
        unsigned* a = AsBase + buf * 128 * 36;
        unsigned* b = BsBase + buf * 128 * 36;
        #pragma unroll
        for (int p = 0; p < 4; p++) {
            int base = (lrow + p * 32) * 36 + (lc4 >> 2);
            a[base + 0]  = f2tf32(ra[p].x);
            a[base + 8]  = f2tf32(ra[p].y);
            a[base + 16] = f2tf32(ra[p].z);
            a[base + 24] = f2tf32(ra[p].w);
            b[base + 0]  = f2tf32(rb[p].x);
            b[base + 8]  = f2tf32(rb[p].y);
            b[base + 16] = f2tf32(rb[p].z);
            b[base + 24] = f2tf32(rb[p].w);
        }
    };
    auto COMPUTE = [&](int buf) {
        const unsigned* a = AsBase + buf * 128 * 36;
        const unsigned* b = BsBase + buf * 128 * 36;
        U8 af[4][2], bf[4];
        #pragma unroll
        for (int mi = 0; mi < 4; mi++) {
            int r = wm + mi * 16 + grp;
            af[mi][0].v[0] = *(const uint4*)(a + r * 36 + tig * 8);
            af[mi][0].v[1] = *(const uint4*)(a + r * 36 + tig * 8 + 4);
            af[mi][1].v[0] = *(const uint4*)(a + (r + 8) * 36 + tig * 8);
            af[mi][1].v[1] = *(const uint4*)(a + (r + 8) * 36 + tig * 8 + 4);
        }
        #pragma unroll
        for (int ni = 0; ni < 4; ni++) {
            int nb = wn + ni * 8 + grp;
            bf[ni].v[0] = *(const uint4*)(b + nb * 36 + tig * 8);
            bf[ni].v[1] = *(const uint4*)(b + nb * 36 + tig * 8 + 4);
        }
        #pragma unroll
        for (int kk = 0; kk < 4; kk++)
            #pragma unroll
            for (int mi = 0; mi < 4; mi++)
                #pragma unroll
                for (int ni = 0; ni < 4; ni++)
                    mma_tf32(acc[mi][ni],
                             af[mi][0].u[2 * kk], af[mi][1].u[2 * kk],
                             af[mi][0].u[2 * kk + 1], af[mi][1].u[2 * kk + 1],
                             bf[ni].u[2 * kk], bf[ni].u[2 * kk + 1]);
    };

    const int nk = K >> 5;
    LDG(0);
    STS(0);
    if (nk > 1) LDG(32);
    __syncthreads();

    for (int i = 0; i < nk; i++) {
        if (i + 1 < nk) {
            STS((i + 1) & 1);
            if (i + 2 < nk) LDG((i + 2) << 5);
        }
        COMPUTE(i & 1);
        if (i + 1 < nk) __syncthreads();
    }

    float* Cp = C + (size_t)cz * z;
    #pragma unroll
    for (int mi = 0; mi < 4; mi++) {
        int row = blockIdx.y * 128 + wm + mi * 16 + grp;
        #pragma unroll
        for (int ni = 0; ni < 4; ni++) {
            int col = blockIdx.x * 128 + wn + ni * 8 + 2 * tig;
            float b0 = 0.f, b1 = 0.f;
            if (BIAS) { b0 = bias[col]; b1 = bias[col + 1]; }
            float v0 = acc[mi][ni][0] * scale + b0;
            float v1 = acc[mi][ni][1] * scale + b1;
            float v2 = acc[mi][ni][2] * scale + b0;
            float v3 = acc[mi][ni][3] * scale + b1;
            if (RELU) { v0 = fmaxf(v0, 0.f); v1 = fmaxf(v1, 0.f); v2 = fmaxf(v2, 0.f); v3 = fmaxf(v3, 0.f); }
            *(float2*)(Cp + (size_t)row * ldc + col)       = make_float2(v0, v1);
            *(float2*)(Cp + (size_t)(row + 8) * ldc + col) = make_float2(v2, v3);
        }
    }
}

// ============ TF32 NN GEMM: O = att @ V (M=1024, N=64, K=1024 per bh) ============
// BM=128, BN=64, BK=32, warp tiles 64x16, same permuted layout / double buffer.
__global__ __launch_bounds__(256, 1) void gemm_av_tf32(
    const float* __restrict__ S, const float* __restrict__ V, float* __restrict__ O)
{
    extern __shared__ unsigned sm[];
    unsigned* AsBase = sm;                 // [2][128*36]
    unsigned* BsBase = sm + 2 * 128 * 36;  // [2][64*36]

    const int z = blockIdx.z;
    const float* Ap = S + (size_t)z * Ss * Ss + (size_t)(blockIdx.y * 128) * Ss;
    const float* Bp = V + (size_t)z * Ss * HDh;
    const int tid = threadIdx.x;
    const int lane = tid & 31, warp = tid >> 5;
    const int wm = (warp >> 2) * 64, wn = (warp & 3) * 16;
    const int grp = lane >> 2, tig = lane & 3;
    const int lrow = tid >> 3;            // 0..31
    const int lc4  = (tid & 7) * 4;
    const int cB = tid >> 6;              // k-class 0..3
    const int nB = tid & 63;              // column 0..63

    float4 ra[4];
    float vb[8];
    float acc[4][2][4] = {};

    auto LDG = [&](int k0) {
        #pragma unroll
        for (int p = 0; p < 4; p++)
            ra[p] = *(const float4*)(Ap + (size_t)(lrow + p * 32) * Ss + k0 + lc4);
        #pragma unroll
        for (int t = 0; t < 8; t++)
            vb[t] = Bp[(size_t)(k0 + cB + 4 * t) * HDh + nB];
    };
    auto STS = [&](int buf) {
        unsigned* a = AsBase + buf * 128 * 36;
        unsigned* b = BsBase + buf * 64 * 36;
        #pragma unroll
        for (int p = 0; p < 4; p++) {
            int base = (lrow + p * 32) * 36 + (lc4 >> 2);
            a[base + 0]  = f2tf32(ra[p].x);
            a[base + 8]  = f2tf32(ra[p].y);
            a[base + 16] = f2tf32(ra[p].z);
            a[base + 24] = f2tf32(ra[p].w);
        }
        uint4 w0 = make_uint4(f2tf32(vb[0]), f2tf32(vb[1]), f2tf32(vb[2]), f2tf32(vb[3]));
        uint4 w1 = make_uint4(f2tf32(vb[4]), f2tf32(vb[5]), f2tf32(vb[6]), f2tf32(vb[7]));
        *(uint4*)(b + nB * 36 + cB * 8)     = w0;
        *(uint4*)(b + nB * 36 + cB * 8 + 4) = w1;
    };
    auto COMPUTE = [&](int buf) {
        const unsigned* a = AsBase + buf * 128 * 36;
        const unsigned* b = BsBase + buf * 64 * 36;
        U8 af[4][2], bf[2];
        #pragma unroll
        for (int mi = 0; mi < 4; mi++) {
            int r = wm + mi * 16 + grp;
            af[mi][0].v[0] = *(const uint4*)(a + r * 36 + tig * 8);
            af[mi][0].v[1] = *(const uint4*)(a + r * 36 + tig * 8 + 4);
            af[mi][1].v[0] = *(const uint4*)(a + (r + 8) * 36 + tig * 8);
            af[mi][1].v[1] = *(const uint4*)(a + (r + 8) * 36 + tig * 8 + 4);
        }
        #pragma unroll
        for (int ni = 0; ni < 2; ni++) {
            int nb = wn + ni * 8 + grp;
            bf[ni].v[0] = *(const uint4*)(b + nb * 36 + tig * 8);
            bf[ni].v[1] = *(const uint4*)(b + nb * 36 + tig * 8 + 4);
        }
        #pragma unroll
        for (int kk = 0; kk < 4; kk++)
            #pragma unroll
            for (int mi = 0; mi < 4; mi++)
                #pragma unroll
                for (int ni = 0; ni < 2; ni++)
                    mma_tf32(acc[mi][ni],
                             af[mi][0].u[2 * kk], af[mi][1].u[2 * kk],
                             af[mi][0].u[2 * kk + 1], af[mi][1].u[2 * kk + 1],
                             bf[ni].u[2 * kk], bf[ni].u[2 * kk + 1]);
    };

    const int nk = Ss >> 5;   // 32
    LDG(0);
    STS(0);
    LDG(32);
    __syncthreads();

    for (int i = 0; i < nk; i++) {
        if (i + 1 < nk) {
            STS((i + 1) & 1);
            if (i + 2 < nk) LDG((i + 2) << 5);
        }
        COMPUTE(i & 1);
        if (i + 1 < nk) __syncthreads();
    }

    const int b = z / Hh, h = z % Hh;
    float* Op = O + (size_t)b * Ss * Dd + (size_t)h * HDh;
    #pragma unroll
    for (int mi = 0; mi < 4; mi++) {
        int row = blockIdx.y * 128 + wm + mi * 16 + grp;
        #pragma unroll
        for (int ni = 0; ni < 2; ni++) {
            int col = wn + ni * 8 + 2 * tig;
            *(float2*)(Op + (size_t)row * Dd + col)       = make_float2(acc[mi][ni][0], acc[mi][ni][1]);
            *(float2*)(Op + (size_t)(row + 8) * Dd + col) = make_float2(acc[mi][ni][2], acc[mi][ni][3]);
        }
    }
}

// ---------------- softmax over rows of 1024 ----------------
__global__ __launch_bounds__(256) void softmax_kernel(float* __restrict__ Sb) {
    float* p = Sb + (size_t)blockIdx.x * Ss;
    float4 v = ((float4*)p)[threadIdx.x];
    float m = fmaxf(fmaxf(v.x, v.y), fmaxf(v.z, v.w));
    m = blockReduceMax(m);
    float e0 = __expf(v.x - m), e1 = __expf(v.y - m), e2 = __expf(v.z - m), e3 = __expf(v.w - m);
    float s = blockReduceSum(e0 + e1 + e2 + e3);
    float inv = 1.f / s;
    float4 o = {e0 * inv, e1 * inv, e2 * inv, e3 * inv};
    ((float4*)p)[threadIdx.x] = o;
}

// ---------------- add + layernorm ----------------
__global__ __launch_bounds__(256) void add_ln_kernel(
    const float* __restrict__ x, const float* __restrict__ h,
    const float* __restrict__ g, const float* __restrict__ bias, float* __restrict__ out)
{
    const size_t row = blockIdx.x;
    const float* px = x + row * Dd;
    const float* ph = h + row * Dd;
    int t = threadIdx.x;
    float v[3];
    #pragma unroll
    for (int i = 0; i < 3; i++) v[i] = px[t + i * 256] + ph[t + i * 256];
    float mu = blockReduceSum(v[0] + v[1] + v[2]) * (1.f / Dd);
    float q = 0.f;
    #pragma unroll
    for (int i = 0; i < 3; i++) { float d = v[i] - mu; q += d * d; }
    float var = blockReduceSum(q) * (1.f / Dd);
    float inv = rsqrtf(var + 1e-5f);
    float* po = out + row * Dd;
    #pragma unroll
    for (int i = 0; i < 3; i++) {
        int c = t + i * 256;
        po[c] = (v[i] - mu) * inv * g[c] + bias[c];
    }
}

// ---------------- host launcher ----------------
extern "C" void kernel_launch(void* const* d_in, const int* in_sizes, int n_in,
                              void* d_out, int out_size) {
    const int*   ids  = (const int*)  d_in[0];
    const float* emb  = (const float*)d_in[1];
    const float* pe   = (const float*)d_in[2];
    const float* Wq   = (const float*)d_in[3];
    const float* bq   = (const float*)d_in[4];
    const float* Wk   = (const float*)d_in[5];
    const float* bk   = (const float*)d_in[6];
    const float* Wv   = (const float*)d_in[7];
    const float* bv   = (const float*)d_in[8];
    const float* W1   = (const float*)d_in[9];
    const float* b1   = (const float*)d_in[10];
    const float* W2   = (const float*)d_in[11];
    const float* b2   = (const float*)d_in[12];
    const float* ln1g = (const float*)d_in[13];
    const float* ln1b = (const float*)d_in[14];
    const float* ln2g = (const float*)d_in[15];
    const float* ln2b = (const float*)d_in[16];

    const int NT_SMEM = 2 * (128 * 36 + 128 * 36) * 4;   // 73728
    const int AV_SMEM = (2 * 128 * 36 + 2 * 64 * 36) * 4; // 55296
    cudaFuncSetAttribute(gemm_tf32_nt<true,  false>, cudaFuncAttributeMaxDynamicSharedMemorySize, NT_SMEM);
    cudaFuncSetAttribute(gemm_tf32_nt<true,  true >, cudaFuncAttributeMaxDynamicSharedMemorySize, NT_SMEM);
    cudaFuncSetAttribute(gemm_tf32_nt<false, false>, cudaFuncAttributeMaxDynamicSharedMemorySize, NT_SMEM);
    cudaFuncSetAttribute(gemm_av_tf32, cudaFuncAttributeMaxDynamicSharedMemorySize, AV_SMEM);

    float *X, *Q, *K, *V, *Sb, *Hb, *Y1, *F;
    cudaGetSymbolAddress((void**)&X,  gX);
    cudaGetSymbolAddress((void**)&Q,  gQ);
    cudaGetSymbolAddress((void**)&K,  gK);
    cudaGetSymbolAddress((void**)&V,  gV);
    cudaGetSymbolAddress((void**)&Sb, gS);
    cudaGetSymbolAddress((void**)&Hb, gHb);
    cudaGetSymbolAddress((void**)&Y1, gY1);
    cudaGetSymbolAddress((void**)&F,  gF);

    const int M = Bb * Ss;   // 8192

    embed_kernel<<<(Bb * Ss * Dd) / 256, 256>>>(ids, emb, pe, X);

    for (int l = 0; l < LL; l++) {
        const float* wq = Wq + (size_t)l * Dd * Dd;
        const float* wk = Wk + (size_t)l * Dd * Dd;
        const float* wv = Wv + (size_t)l * Dd * Dd;
        const float* w1 = W1 + (size_t)l * DFF * Dd;
        const float* w2 = W2 + (size_t)l * Dd * DFF;

        dim3 gQKV(Dd / 128, M / 128, 1);
        gemm_tf32_nt<true, false><<<gQKV, 256, NT_SMEM>>>(M, Dd, Dd, X, Dd, 0, wq, Dd, 0, Q, Dd, 0, bq + l * Dd, 1.f);
        gemm_tf32_nt<true, false><<<gQKV, 256, NT_SMEM>>>(M, Dd, Dd, X, Dd, 0, wk, Dd, 0, K, Dd, 0, bk + l * Dd, 1.f);
        gemm_tf32_nt<true, false><<<gQKV, 256, NT_SMEM>>>(M, Dd, Dd, X, Dd, 0, wv, Dd, 0, V, Dd, 0, bv + l * Dd, 1.f);

        gemm_tf32_nt<false, false><<<dim3(Ss / 128, Ss / 128, Bb * Hh), 256, NT_SMEM>>>(
            Ss, Ss, HDh, Q, HDh, (long)Ss * HDh, K, HDh, (long)Ss * HDh,
            Sb, Ss, (long)Ss * Ss, nullptr, 0.125f);

        softmax_kernel<<<Bb * Hh * Ss, 256>>>(Sb);

        gemm_av_tf32<<<dim3(1, Ss / 128, Bb * Hh), 256, AV_SMEM>>>(Sb, V, Hb);

        add_ln_kernel<<<M, 256>>>(X, Hb, ln1g + l * Dd, ln1b + l * Dd, Y1);

        gemm_tf32_nt<true, true><<<dim3(DFF / 128, M / 128, 1), 256, NT_SMEM>>>(
            M, DFF, Dd, Y1, Dd, 0, w1, Dd, 0, F, DFF, 0, b1 + l * DFF, 1.f);
        gemm_tf32_nt<true, false><<<dim3(Dd / 128, M / 128, 1), 256, NT_SMEM>>>(
            M, Dd, DFF, F, DFF, 0, w2, DFF, 0, Hb, Dd, 0, b2 + l * Dd, 1.f);

        float* outp = (l == LL - 1) ? (float*)d_out : X;
        add_ln_kernel<<<M, 256>>>(Y1, Hb, ln2g + l * Dd, ln2b + l * Dd, outp);
    }
}